// round 17
// baseline (speedup 1.0000x reference)
#include <cuda_runtime.h>
#include <cuda_bf16.h>
#include <cstdint>

// Problem constants
static constexpr int BATCH = 8;
static constexpr int SEQ   = 2048;
static constexpr int DIM   = 768;
static constexpr long long BSD = (long long)BATCH * SEQ * DIM;

// Scratch (device globals: allocation-free per harness rules). 16B-aligned for cp.async.
__device__ __align__(16) float g_xtf[BATCH * SEQ * DIM];      // x, tf32-rounded
__device__ __align__(16) float g_wt[3 * DIM * DIM];           // W^T per slice, tf32-rounded
__device__ __align__(16) float g_qkv[3 * BATCH * SEQ * DIM];  // q|k|v (tf32-rounded)
__device__ __align__(16) float g_vt[BATCH * DIM * SEQ];       // V^T per batch
__device__ __align__(16) float g_s[BATCH * SEQ * SEQ];        // scores / attn

__device__ __forceinline__ uint32_t f2tf32(float f) {
    uint32_t u;
    asm volatile("cvt.rna.tf32.f32 %0, %1;" : "=r"(u) : "f"(f));
    return u;
}
__device__ __forceinline__ float rna(float f) { return __uint_as_float(f2tf32(f)); }

__device__ __forceinline__ void mma_tf32(
    float& c0, float& c1, float& c2, float& c3,
    uint32_t a0, uint32_t a1, uint32_t a2, uint32_t a3,
    uint32_t b0, uint32_t b1)
{
    asm volatile(
        "mma.sync.aligned.m16n8k8.row.col.f32.tf32.tf32.f32 "
        "{%0,%1,%2,%3}, {%4,%5,%6,%7}, {%8,%9}, {%0,%1,%2,%3};\n"
        : "+f"(c0), "+f"(c1), "+f"(c2), "+f"(c3)
        : "r"(a0), "r"(a1), "r"(a2), "r"(a3), "r"(b0), "r"(b1));
}

__device__ __forceinline__ void ldmx4(uint32_t& r0, uint32_t& r1, uint32_t& r2, uint32_t& r3,
                                      uint32_t saddr)
{
    asm volatile("ldmatrix.sync.aligned.m8n8.x4.shared.b16 {%0,%1,%2,%3}, [%4];"
                 : "=r"(r0), "=r"(r1), "=r"(r2), "=r"(r3) : "r"(saddr));
}

__device__ __forceinline__ void cp16(void* smem_dst, const void* gsrc) {
    uint32_t sa = (uint32_t)__cvta_generic_to_shared(smem_dst);
    asm volatile("cp.async.cg.shared.global [%0], [%1], 16;\n" :: "r"(sa), "l"(gsrc));
}

// ---- mbarrier helpers ----
__device__ __forceinline__ void mbar_init(uint32_t a, uint32_t cnt) {
    asm volatile("mbarrier.init.shared.b64 [%0], %1;" :: "r"(a), "r"(cnt) : "memory");
}
__device__ __forceinline__ void mbar_arrive(uint32_t a) {
    asm volatile("mbarrier.arrive.shared.b64 _, [%0];" :: "r"(a) : "memory");
}
__device__ __forceinline__ void cpasync_mbar_arrive(uint32_t a) {
    asm volatile("cp.async.mbarrier.arrive.noinc.shared.b64 [%0];" :: "r"(a) : "memory");
}
__device__ __forceinline__ void mbar_wait(uint32_t a, uint32_t parity) {
    asm volatile(
        "{\n\t.reg .pred P;\n"
        "WL_%=:\n\t"
        "mbarrier.try_wait.parity.acquire.cta.shared::cta.b64 P, [%0], %1, 0x989680;\n\t"
        "@P bra.uni WD_%=;\n\t"
        "bra.uni WL_%=;\n"
        "WD_%=:\n\t}"
        :: "r"(a), "r"(parity) : "memory");
}

// ---------------------------------------------------------------------------
// tf32 tensor-core GEMM (NT only), 3-stage cp.async + per-stage mbarrier ring.
// C = alpha * A @ B^T; inputs already tf32-rounded.
//   A: [M,K] row-major; B: [N,K] row-major; C: [M,N]
// CTA 128 x (16*NF) x 32, 4 warps (128 threads), warp tile 64 x (8*NF);
// 2 CTAs/SM; ldmatrix both operands; fragment double-buffering.
// R17 (=R16 fixed): NF template (8 -> BN=128 for QKV/scores; 4 -> BN=64 for
// AV). AV grid was 768 CTAs (5.19/SM slot-pair -> 3-round tail ~15% loss);
// BN=64 doubles it to 1536 half-cost CTAs -> ~6% tail.
//   As [m][k] s36 ; Bs [n][k] s36
// full[s]: 128 cp.async arrivals; empty[s]: 4 per-warp arrivals.
// ---------------------------------------------------------------------------
#define BM 128
#define BK 32
#define NTHREADS 128
#define NWARPS 4
#define STAGES 3

static constexpr int TS_STRIDE = BK + 4;                 // 36
static constexpr int ASZ_T = BM * TS_STRIDE;             // floats per A stage
static constexpr int MBAR_FLOATS = 32;                   // 128 B for 3x(full,empty)
// Host+device-safe constexpr helpers (R16 failed: host-only constexpr fn
// called from device; harness has no --expt-relaxed-constexpr).
__host__ __device__ constexpr int BN_of(int NF) { return 16 * NF; }
__host__ __device__ constexpr int BSZ_of(int NF) { return BN_of(NF) * TS_STRIDE; }
__host__ __device__ constexpr int SMEM_of(int NF) {
    return (MBAR_FLOATS + STAGES * (ASZ_T + BSZ_of(NF))) * 4;
}

template <bool ROUND, int NF>
__global__ __launch_bounds__(NTHREADS, 2) void mma_gemm(
    const float* __restrict__ Ab, const float* __restrict__ Bb,
    float* __restrict__ Cb,
    int M, int N, int K,
    long long sA, long long sB, long long sC, float alpha)
{
    constexpr int BN  = 16 * NF;
    constexpr int BSZ = BN * TS_STRIDE;

    const float* A = Ab + (long long)blockIdx.z * sA;
    const float* B = Bb + (long long)blockIdx.z * sB;
    float*       C = Cb + (long long)blockIdx.z * sC;

    extern __shared__ float smem[];
    const uint32_t mb = (uint32_t)__cvta_generic_to_shared(smem);  // mbar area
    float* AsBase = smem + MBAR_FLOATS;
    float* BsBase = AsBase + STAGES * ASZ_T;

    const int tid  = threadIdx.x;
    const int warp = tid >> 5;        // 0..3
    const int lane = tid & 31;
    const int gid  = lane >> 2;       // 0..7
    const int tig  = lane & 3;        // 0..3
    const int wm   = (warp >> 1) * 64;        // 0 or 64
    const int wn   = (warp & 1) * (8 * NF);   // 0 or BN/2
    const int row0 = blockIdx.y * BM;
    const int col0 = blockIdx.x * BN;

    if (tid == 0) {
#pragma unroll
        for (int s = 0; s < STAGES; s++) {
            mbar_init(mb + s * 16, NTHREADS);   // full: one cp.async arrive per thread
            mbar_init(mb + s * 16 + 8, NWARPS); // empty: one arrive per warp
        }
    }
    __syncthreads();
    if (lane == 0) {
#pragma unroll
        for (int s = 0; s < STAGES; s++) mbar_arrive(mb + s * 16 + 8);
    }

    // ldmatrix per-lane byte offsets (verified R10-R15)
    const uint32_t laneAOff = (uint32_t)((lane & 15) * TS_STRIDE * 4 + (lane & 16));
    const uint32_t laneBOff = (uint32_t)(((lane & 7) + ((lane & 16) >> 1)) * TS_STRIDE * 4
                                         + (lane & 8) * 2);

    // Accumulators: 4 m-frags x NF n-frags x 4 regs
    float c[4][NF][4];
#pragma unroll
    for (int i = 0; i < 4; i++)
#pragma unroll
        for (int j = 0; j < NF; j++)
#pragma unroll
            for (int r = 0; r < 4; r++) c[i][j][r] = 0.f;

    const int aR = tid >> 3;            // 0..15 (+16/pass), 16B along k
    const int aC = (tid & 7) * 4;

    auto load_tile = [&](int stage, int kt) {
        float* As = AsBase + stage * ASZ_T;
        float* Bs = BsBase + stage * BSZ;
#pragma unroll
        for (int p = 0; p < BM / 16; p++) {
            int r = aR + p * 16;
            cp16(&As[r * TS_STRIDE + aC], A + (long long)(row0 + r) * K + kt + aC);
        }
#pragma unroll
        for (int p = 0; p < BN / 16; p++) {
            int r = aR + p * 16;
            cp16(&Bs[r * TS_STRIDE + aC], B + (long long)(col0 + r) * K + kt + aC);
        }
    };

    const int T = K / BK;

    // Producer cursor
    int ps = 0, pp = 0;
#pragma unroll
    for (int i = 0; i < STAGES; i++) {
        if (i < T) {
            mbar_wait(mb + ps * 16 + 8, pp);
            load_tile(ps, i * BK);
            cpasync_mbar_arrive(mb + ps * 16);
            if (++ps == STAGES) { ps = 0; pp ^= 1; }
        }
    }

    // Consumer cursor
    int cs = 0, cph = 0;
    for (int t = 0; t < T; t++) {
        mbar_wait(mb + cs * 16, cph);

        float* AsF = AsBase + cs * ASZ_T;
        float* BsF = BsBase + cs * BSZ;
        const uint32_t asAddr = (uint32_t)__cvta_generic_to_shared(AsF) + laneAOff;
        const uint32_t bsAddr = (uint32_t)__cvta_generic_to_shared(BsF) + laneBOff;

        // Double-buffered fragments: load ks+1 under the MMAs of ks.
        uint32_t a[2][4][4];
        uint32_t b[2][NF][2];

#pragma unroll
        for (int i = 0; i < 4; i++)
            ldmx4(a[0][i][0], a[0][i][1], a[0][i][2], a[0][i][3],
                  asAddr + (uint32_t)(((wm + 16 * i) * TS_STRIDE) * 4));
#pragma unroll
        for (int jp = 0; jp < NF / 2; jp++)
            ldmx4(b[0][2 * jp][0], b[0][2 * jp][1], b[0][2 * jp + 1][0], b[0][2 * jp + 1][1],
                  bsAddr + (uint32_t)(((wn + 16 * jp) * TS_STRIDE) * 4));

#pragma unroll
        for (int kk = 0; kk < BK / 8; kk++) {
            const int cur = kk & 1;
            if (kk < BK / 8 - 1) {
                const int nxt = cur ^ 1;
                const int ks = (kk + 1) * 8;
#pragma unroll
                for (int i = 0; i < 4; i++)
                    ldmx4(a[nxt][i][0], a[nxt][i][1], a[nxt][i][2], a[nxt][i][3],
                          asAddr + (uint32_t)(((wm + 16 * i) * TS_STRIDE + ks) * 4));
#pragma unroll
                for (int jp = 0; jp < NF / 2; jp++)
                    ldmx4(b[nxt][2 * jp][0], b[nxt][2 * jp][1],
                          b[nxt][2 * jp + 1][0], b[nxt][2 * jp + 1][1],
                          bsAddr + (uint32_t)(((wn + 16 * jp) * TS_STRIDE + ks) * 4));
            } else {
                // Last smem read of this stage already issued: free the stage now.
                if (lane == 0) mbar_arrive(mb + cs * 16 + 8);
            }
#pragma unroll
            for (int i = 0; i < 4; i++)
#pragma unroll
                for (int j = 0; j < NF; j++)
                    mma_tf32(c[i][j][0], c[i][j][1], c[i][j][2], c[i][j][3],
                             a[cur][i][0], a[cur][i][1], a[cur][i][2], a[cur][i][3],
                             b[cur][j][0], b[cur][j][1]);
        }

        if (++cs == STAGES) { cs = 0; cph ^= 1; }

        int nt = t + STAGES;
        if (nt < T) {
            mbar_wait(mb + ps * 16 + 8, pp);
            load_tile(ps, nt * BK);
            cpasync_mbar_arrive(mb + ps * 16);
            if (++ps == STAGES) { ps = 0; pp ^= 1; }
        }
    }

#pragma unroll
    for (int i = 0; i < 4; i++) {
        int rowA = row0 + wm + 16 * i + gid;
#pragma unroll
        for (int j = 0; j < NF; j++) {
            int col = col0 + wn + 8 * j + 2 * tig;
            float f0 = c[i][j][0] * alpha, f1 = c[i][j][1] * alpha;
            float f2 = c[i][j][2] * alpha, f3 = c[i][j][3] * alpha;
            if (ROUND) { f0 = rna(f0); f1 = rna(f1); f2 = rna(f2); f3 = rna(f3); }
            *(float2*)(C + (long long)rowA * N + col) = make_float2(f0, f1);
            *(float2*)(C + (long long)(rowA + 8) * N + col) = make_float2(f2, f3);
        }
    }
}

// ---------------------------------------------------------------------------
// Elementwise tf32 rounding (prep)
// ---------------------------------------------------------------------------
__global__ __launch_bounds__(256) void cvt_rna_kernel(
    const float* __restrict__ in, float* __restrict__ out)
{
    int i = (blockIdx.x * 256 + threadIdx.x) * 4;
    float4 v = *(const float4*)(in + i);
    v.x = rna(v.x); v.y = rna(v.y); v.z = rna(v.z); v.w = rna(v.w);
    *(float4*)(out + i) = v;
}

// out[z][c][r] = rna(in[z][r][c]); in: R x C per z slice (out stride = R)
__global__ __launch_bounds__(256) void transpose_cvt(
    const float* __restrict__ in, float* __restrict__ out,
    int R, int Ccols, long long zStride)
{
    __shared__ float t[32][33];
    const float* inz  = in  + blockIdx.z * zStride;
    float*       outz = out + blockIdx.z * zStride;
    const int r0 = blockIdx.y * 32;
    const int c0 = blockIdx.x * 32;
    const int tx = threadIdx.x & 31;
    const int ty = threadIdx.x >> 5;   // 0..7
#pragma unroll
    for (int k = 0; k < 4; k++)
        t[ty + k * 8][tx] = inz[(long long)(r0 + ty + k * 8) * Ccols + c0 + tx];
    __syncthreads();
#pragma unroll
    for (int k = 0; k < 4; k++)
        outz[(long long)(c0 + ty + k * 8) * R + r0 + tx] = rna(t[tx][ty + k * 8]);
}

// ---------------------------------------------------------------------------
// Row softmax over 2048 columns; float4 I/O; writes tf32-rounded probabilities
// ---------------------------------------------------------------------------
__global__ __launch_bounds__(256) void softmax2048(float* __restrict__ S)
{
    float4* row4 = (float4*)(S + (long long)blockIdx.x * SEQ);
    const int tid = threadIdx.x;

    float4 va = row4[tid];
    float4 vb = row4[tid + 256];
    float x[8] = {va.x, va.y, va.z, va.w, vb.x, vb.y, vb.z, vb.w};

    float m = x[0];
#pragma unroll
    for (int i = 1; i < 8; i++) m = fmaxf(m, x[i]);
#pragma unroll
    for (int o = 16; o > 0; o >>= 1)
        m = fmaxf(m, __shfl_xor_sync(0xffffffffu, m, o));

    __shared__ float red[8];
    if ((tid & 31) == 0) red[tid >> 5] = m;
    __syncthreads();
    float mAll = red[0];
#pragma unroll
    for (int i = 1; i < 8; i++) mAll = fmaxf(mAll, red[i]);
    __syncthreads();

    float s = 0.f;
#pragma unroll
    for (int i = 0; i < 8; i++) {
        x[i] = __expf(x[i] - mAll);
        s += x[i];
    }
#pragma unroll
    for (int o = 16; o > 0; o >>= 1)
        s += __shfl_xor_sync(0xffffffffu, s, o);
    if ((tid & 31) == 0) red[tid >> 5] = s;
    __syncthreads();
    float tot = 0.f;
#pragma unroll
    for (int i = 0; i < 8; i++) tot += red[i];

    const float inv = 1.f / tot;
#pragma unroll
    for (int i = 0; i < 8; i++) x[i] = rna(x[i] * inv);
    row4[tid]       = make_float4(x[0], x[1], x[2], x[3]);
    row4[tid + 256] = make_float4(x[4], x[5], x[6], x[7]);
}

// ---------------------------------------------------------------------------
// Launch
// ---------------------------------------------------------------------------
extern "C" void kernel_launch(void* const* d_in, const int* in_sizes, int n_in,
                              void* d_out, int out_size)
{
    const float* x = (const float*)d_in[0];   // [8, 2048, 768]
    const float* w = (const float*)d_in[1];   // [3, 768, 768]
    float* out     = (float*)d_out;           // [8, 2048, 768]

    float *xtf, *wt, *qkv, *vt, *sc;
    cudaGetSymbolAddress((void**)&xtf, g_xtf);
    cudaGetSymbolAddress((void**)&wt,  g_wt);
    cudaGetSymbolAddress((void**)&qkv, g_qkv);
    cudaGetSymbolAddress((void**)&vt,  g_vt);
    cudaGetSymbolAddress((void**)&sc,  g_s);

    const float INV_SCALE = 0.125f;  // 1 / sqrt(64)

    constexpr int SMEM8 = SMEM_of(8);
    constexpr int SMEM4 = SMEM_of(4);

    cudaFuncSetAttribute(mma_gemm<true, 8>,
                         cudaFuncAttributeMaxDynamicSharedMemorySize, SMEM8);
    cudaFuncSetAttribute(mma_gemm<false, 8>,
                         cudaFuncAttributeMaxDynamicSharedMemorySize, SMEM8);
    cudaFuncSetAttribute(mma_gemm<false, 4>,
                         cudaFuncAttributeMaxDynamicSharedMemorySize, SMEM4);

    // 0) x -> tf32-rounded; W -> W^T tf32-rounded (all GEMMs are NT)
    cvt_rna_kernel<<<(BATCH * SEQ * DIM) / 1024, 256>>>(x, xtf);
    transpose_cvt<<<dim3(DIM / 32, DIM / 32, 3), 256>>>(
        w, wt, DIM, DIM, (long long)DIM * DIM);

    // 1) QKV (NT, BN=128): qkv[z] = xtf @ wt[z]^T; outputs tf32-rounded
    {
        dim3 grid(DIM / 128, (BATCH * SEQ) / BM, 3);
        mma_gemm<true, 8><<<grid, NTHREADS, SMEM8>>>(xtf, wt, qkv,
                                       BATCH * SEQ, DIM, DIM,
                                       0LL, (long long)DIM * DIM, BSD, 1.0f);
    }

    // 1b) V -> V^T per batch (rna idempotent on already-rounded values)
    transpose_cvt<<<dim3(DIM / 32, SEQ / 32, BATCH), 256>>>(
        qkv + 2 * BSD, vt, SEQ, DIM, (long long)SEQ * DIM);

    // 2) scores = Q @ K^T / 8  (NT, BN=128, batched over 8)
    {
        dim3 grid(SEQ / 128, SEQ / BM, BATCH);
        mma_gemm<false, 8><<<grid, NTHREADS, SMEM8>>>(qkv, qkv + BSD, sc,
                                      SEQ, SEQ, DIM,
                                      (long long)SEQ * DIM, (long long)SEQ * DIM,
                                      (long long)SEQ * SEQ, INV_SCALE);
    }

    // 3) softmax over last dim; writes tf32-rounded attn
    softmax2048<<<BATCH * SEQ, 256>>>(sc);

    // 4) out = attn @ (V^T)^T  (NT, BN=64 for finer work-steal granularity)
    {
        dim3 grid(DIM / 64, SEQ / BM, BATCH);   // 12 x 16 x 8 = 1536 CTAs
        mma_gemm<false, 4><<<grid, NTHREADS, SMEM4>>>(sc, vt, out,
                                       SEQ, DIM, SEQ,
                                       (long long)SEQ * SEQ, (long long)DIM * SEQ,
                                       (long long)SEQ * DIM, 1.0f);
    }
}